// round 13
// baseline (speedup 1.0000x reference)
#include <cuda_runtime.h>
#include <cstdint>

// Problem shapes (fixed by the dataset)
#define NN   50000
#define DN   256
#define EE   1600000
#define DE   128
#define BB   512
#define DU   128
#define DIN  512      // DU + DN + DE
#define HID  512
#define DOUT 128
// Edges/segment track NODE counts per segment: mean 3125, sd ~316.
// Max over 512 segments ~ 4240. CAP=6144 gives ~9.5 sigma headroom.
#define CAP  6144
#define EBLK 512       // edge-binning CTAs
#define EPB  (EE/EBLK) // 3125 edges per binning CTA
#define EPART 4        // per-segment partitions in the reduction kernel

// ---------------- scratch (device globals: no allocation allowed) ----------------
__device__ float g_xsum[BB * DN];        // node feature sums per graph
__device__ int   g_xcnt[BB];             // nodes per graph
__device__ float g_esum[BB * DE];        // edge feature sums per graph
__device__ int   g_ecnt[BB];             // edges per graph (also bucket allocator)
__device__ int   g_bucket[BB * CAP];     // edge ids bucketed by segment
__device__ float g_h[BB * HID];          // post-GEMM1 hidden
__device__ float g_bns[HID], g_bnsq[HID];// BN partial sums
__device__ int   g_idx64;                // 1 if indices are int64, 0 if int32

// dtype-agnostic index load
__device__ __forceinline__ int ld_idx(const void* p, long long i, int is64) {
    return is64 ? (int)((const long long*)p)[i] : ((const int*)p)[i];
}

// ---------------- K0: zero scratch + detect index width ----------------
__global__ void k_zero_detect(const int* __restrict__ ei32) {
    int gid = blockIdx.x * blockDim.x + threadIdx.x;
    int stride = gridDim.x * blockDim.x;
    for (int i = gid; i < BB * DN; i += stride) g_xsum[i] = 0.f;
    for (int i = gid; i < BB * DE; i += stride) g_esum[i] = 0.f;
    if (blockIdx.x == 0) {
        int t = threadIdx.x;
        for (int i = t; i < BB; i += 256) { g_xcnt[i] = 0; g_ecnt[i] = 0; }
        for (int i = t; i < HID; i += 256) { g_bns[i] = 0.f; g_bnsq[i] = 0.f; }
        // If edge_index is int64 (values nonneg < 2^31), every odd 32-bit word
        // of the first 1024 entries is 0. If int32, those words are random node
        // ids; all-zero probability ~ (1/50000)^1024.
        int nz = 0;
        for (int i = t; i < 1024; i += 256) nz |= ei32[2 * i + 1];
        __shared__ int snz;
        if (t == 0) snz = 0;
        __syncthreads();
        if (nz) atomicOr(&snz, 1);
        __syncthreads();
        if (t == 0) g_idx64 = snz ? 0 : 1;
    }
}

// ---------------- K1: node scatter-mean (batch is SORTED -> run compression) ----
__global__ void __launch_bounds__(256) k_node(const float* __restrict__ x,
                                              const void* __restrict__ batch) {
    const int is64 = g_idx64;
    int t = threadIdx.x;                 // owns dim t (0..255)
    int n0 = blockIdx.x * 100;
    int n1 = min(n0 + 100, NN);
    int cur = -1, runlen = 0;
    float acc = 0.f;
    for (int n = n0; n < n1; n++) {
        int s = ld_idx(batch, n, is64);
        if (s != cur) {
            if (cur >= 0) {
                atomicAdd(&g_xsum[cur * DN + t], acc);
                if (t == 0) atomicAdd(&g_xcnt[cur], runlen);
            }
            cur = s; acc = 0.f; runlen = 0;
        }
        acc += x[(long long)n * DN + t];
        runlen++;
    }
    if (cur >= 0) {
        atomicAdd(&g_xsum[cur * DN + t], acc);
        if (t == 0) atomicAdd(&g_xcnt[cur], runlen);
    }
}

// ---------------- K2: bin edges into per-segment buckets ----------------
__global__ void __launch_bounds__(256) k_edge_bucket(const void* __restrict__ eidx,
                                                     const void* __restrict__ batch) {
    __shared__ int shist[BB];
    __shared__ int sbase[BB];
    __shared__ unsigned short ssegs[EPB];
    const int is64 = g_idx64;
    int t = threadIdx.x;
    int e0 = blockIdx.x * EPB;
    for (int s = t; s < BB; s += 256) shist[s] = 0;
    __syncthreads();
    // phase 1: segment per edge + local histogram
    for (int it = t; it < EPB; it += 256) {
        int c = ld_idx(eidx, (long long)EE + (e0 + it), is64);  // col = edge_index[1][e]
        int s = ld_idx(batch, c, is64);
        ssegs[it] = (unsigned short)s;
        atomicAdd(&shist[s], 1);
    }
    __syncthreads();
    // phase 2: claim contiguous global ranges (1 global atomic per present seg)
    for (int s = t; s < BB; s += 256) {
        int n = shist[s];
        sbase[s] = n ? atomicAdd(&g_ecnt[s], n) : 0;
        shist[s] = 0;
    }
    __syncthreads();
    // phase 3: scatter edge ids
    for (int it = t; it < EPB; it += 256) {
        int s = ssegs[it];
        int r = atomicAdd(&shist[s], 1);
        int pos = sbase[s] + r;
        if (pos < CAP) g_bucket[s * CAP + pos] = e0 + it;
    }
}

// ---------------- K3: per-segment edge reduction, 4-way partitioned ----------
// grid (BB, EPART). Each CTA reduces a quarter of one segment's bucket in
// registers, then atomicAdds its 128-dim partial (2048 spread-address float
// atomics per segment total -> negligible vs the 819MB gather).
// Edge ids for iteration n+1 are prefetched during iteration n so the L2-hit
// latency of the id loads (~234cyc) hides entirely under the data gathers.
__global__ void __launch_bounds__(256) k_eaggr(const float* __restrict__ ea) {
    __shared__ float4 sacc[8][32];
    int s = blockIdx.x;
    int p = blockIdx.y;
    int w = threadIdx.x >> 5, lane = threadIdx.x & 31;
    int cnt = min(g_ecnt[s], CAP);
    int i0 = (cnt * p) / EPART;
    int i1 = (cnt * (p + 1)) / EPART;
    const int* bkt = &g_bucket[s * CAP];
    float4 a = make_float4(0.f, 0.f, 0.f, 0.f);
    int i = i0 + w;
    int e0 = 0, e1 = 0, e2 = 0, e3 = 0;
    bool have = (i + 24 < i1);
    if (have) {
        e0 = bkt[i]; e1 = bkt[i + 8]; e2 = bkt[i + 16]; e3 = bkt[i + 24];
    }
    while (have) {
        int ni = i + 32;
        bool nhave = (ni + 24 < i1);
        int f0 = 0, f1 = 0, f2 = 0, f3 = 0;
        if (nhave) {            // prefetch next ids before issuing data gathers
            f0 = bkt[ni]; f1 = bkt[ni + 8]; f2 = bkt[ni + 16]; f3 = bkt[ni + 24];
        }
        float4 v0 = ((const float4*)(ea + (long long)e0 * DE))[lane];
        float4 v1 = ((const float4*)(ea + (long long)e1 * DE))[lane];
        float4 v2 = ((const float4*)(ea + (long long)e2 * DE))[lane];
        float4 v3 = ((const float4*)(ea + (long long)e3 * DE))[lane];
        a.x += v0.x + v1.x + v2.x + v3.x;
        a.y += v0.y + v1.y + v2.y + v3.y;
        a.z += v0.z + v1.z + v2.z + v3.z;
        a.w += v0.w + v1.w + v2.w + v3.w;
        i = ni; e0 = f0; e1 = f1; e2 = f2; e3 = f3; have = nhave;
    }
    for (; i < i1; i += 8) {
        int e = bkt[i];
        float4 v = ((const float4*)(ea + (long long)e * DE))[lane];
        a.x += v.x; a.y += v.y; a.z += v.z; a.w += v.w;
    }
    sacc[w][lane] = a;
    __syncthreads();
    if (w == 0) {
        float4 tt = sacc[0][lane];
        #pragma unroll
        for (int j = 1; j < 8; j++) {
            float4 v = sacc[j][lane];
            tt.x += v.x; tt.y += v.y; tt.z += v.z; tt.w += v.w;
        }
        float* dst = &g_esum[s * DE + lane * 4];
        atomicAdd(dst + 0, tt.x);
        atomicAdd(dst + 1, tt.y);
        atomicAdd(dst + 2, tt.z);
        atomicAdd(dst + 3, tt.w);
    }
}

// ---------------- K5: GEMM1 with fused concat-build + BN partial stats -------
// A-tile built on the fly from u / x_mean / e_mean; epilogue accumulates
// per-column BN sum/sumsq partials (64 y-blocks -> 64-way atomic fan-in).
__global__ void __launch_bounds__(128) k_gemm1(const float* __restrict__ u,
                                               const float* __restrict__ W1,
                                               const float* __restrict__ b1) {
    __shared__ __align__(16) float sA[8 * DIN];
    __shared__ float sinvx[8], sinve[8];
    int r0 = blockIdx.y * 8;
    int col = blockIdx.x * 128 + threadIdx.x;
    if (threadIdx.x < 8) {
        int row = r0 + threadIdx.x;
        sinvx[threadIdx.x] = 1.f / (float)max(g_xcnt[row], 1);
        sinve[threadIdx.x] = 1.f / (float)max(g_ecnt[row], 1);
    }
    __syncthreads();
    for (int i = threadIdx.x; i < 8 * DIN; i += 128) {
        int r = i >> 9, k = i & (DIN - 1);
        int row = r0 + r;
        float v;
        if (k < 128)       v = u[row * DU + k];
        else if (k < 384)  v = g_xsum[row * DN + (k - 128)] * sinvx[r];
        else               v = g_esum[row * DE + (k - 384)] * sinve[r];
        sA[i] = v;
    }
    __syncthreads();
    float acc[8];
    #pragma unroll
    for (int r = 0; r < 8; r++) acc[r] = 0.f;
    for (int k = 0; k < DIN; k += 4) {
        float w0 = __ldg(&W1[(k + 0) * HID + col]);
        float w1 = __ldg(&W1[(k + 1) * HID + col]);
        float w2 = __ldg(&W1[(k + 2) * HID + col]);
        float w3 = __ldg(&W1[(k + 3) * HID + col]);
        #pragma unroll
        for (int r = 0; r < 8; r++) {
            float4 av = *(const float4*)&sA[r * DIN + k];
            acc[r] += av.x * w0 + av.y * w1 + av.z * w2 + av.w * w3;
        }
    }
    float bb = b1[col];
    float ps = 0.f, psq = 0.f;
    #pragma unroll
    for (int r = 0; r < 8; r++) {
        float v = acc[r] + bb;
        g_h[(r0 + r) * HID + col] = v;
        ps += v; psq += v * v;
    }
    atomicAdd(&g_bns[col], ps);
    atomicAdd(&g_bnsq[col], psq);
}

// ---------------- K8: GEMM2 with fused BN-finalize + BN+ReLU on input read ---
// Each CTA recomputes the 512 scale/shift pairs from the completed g_bns/g_bnsq
// (cheap: 512 loads + rsqrt per CTA; dependency guaranteed by launch boundary).
__global__ void __launch_bounds__(128) k_gemm2(const float* __restrict__ gamma,
                                               const float* __restrict__ beta,
                                               const float* __restrict__ W2,
                                               const float* __restrict__ b2,
                                               float* __restrict__ out) {
    __shared__ __align__(16) float sA[8 * HID];
    __shared__ float sscale[HID], sshift[HID];
    int r0 = blockIdx.y * 8;
    int col = threadIdx.x;  // 128 cols
    for (int j = threadIdx.x; j < HID; j += 128) {
        float m = g_bns[j] * (1.f / (float)BB);
        float var = g_bnsq[j] * (1.f / (float)BB) - m * m;
        float inv = rsqrtf(var + 1e-5f);
        float sc = gamma[j] * inv;
        sscale[j] = sc;
        sshift[j] = beta[j] - m * sc;
    }
    __syncthreads();
    for (int i = threadIdx.x; i < 8 * HID; i += 128) {
        int k = i & (HID - 1);
        float v = g_h[r0 * HID + i] * sscale[k] + sshift[k];
        sA[i] = fmaxf(v, 0.f);
    }
    __syncthreads();
    float acc[8];
    #pragma unroll
    for (int r = 0; r < 8; r++) acc[r] = 0.f;
    for (int k = 0; k < HID; k += 4) {
        float w0 = __ldg(&W2[(k + 0) * DOUT + col]);
        float w1 = __ldg(&W2[(k + 1) * DOUT + col]);
        float w2 = __ldg(&W2[(k + 2) * DOUT + col]);
        float w3 = __ldg(&W2[(k + 3) * DOUT + col]);
        #pragma unroll
        for (int r = 0; r < 8; r++) {
            float4 av = *(const float4*)&sA[r * HID + k];
            acc[r] += av.x * w0 + av.y * w1 + av.z * w2 + av.w * w3;
        }
    }
    float bb = b2[col];
    #pragma unroll
    for (int r = 0; r < 8; r++) out[(r0 + r) * DOUT + col] = acc[r] + bb;
}

// ---------------- launch ----------------
extern "C" void kernel_launch(void* const* d_in, const int* in_sizes, int n_in,
                              void* d_out, int out_size) {
    const float* x  = (const float*)d_in[0];
    const void*  ei = d_in[1];                  // edge_index [2, E] (int32 or int64)
    const float* ea = (const float*)d_in[2];
    const float* u  = (const float*)d_in[3];
    const void*  bt = (const void*)d_in[4];     // batch [N] sorted
    const float* W1 = (const float*)d_in[5];
    const float* b1 = (const float*)d_in[6];
    const float* ga = (const float*)d_in[7];
    const float* be = (const float*)d_in[8];
    const float* W2 = (const float*)d_in[9];
    const float* b2 = (const float*)d_in[10];

    k_zero_detect<<<256, 256>>>((const int*)ei);
    k_node<<<500, 256>>>(x, bt);
    k_edge_bucket<<<EBLK, 256>>>(ei, bt);
    k_eaggr<<<dim3(BB, EPART), 256>>>(ea);
    k_gemm1<<<dim3(4, 64), 128>>>(u, W1, b1);
    k_gemm2<<<dim3(1, 64), 128>>>(ga, be, W2, b2, (float*)d_out);
}

// round 16
// speedup vs baseline: 1.1711x; 1.1711x over previous
#include <cuda_runtime.h>
#include <cstdint>

// Problem shapes (fixed by the dataset)
#define NN   50000
#define DN   256
#define EE   1600000
#define DE   128
#define BB   512
#define DU   128
#define DIN  512      // DU + DN + DE
#define HID  512
#define DOUT 128
// Edges/segment track NODE counts per segment: mean 3125, sd ~316.
// Max over 512 segments ~ 4240. CAP=6144 gives ~9.5 sigma headroom.
#define CAP  6144
#define EBLK 512       // edge-binning CTAs
#define EPB  (EE/EBLK) // 3125 edges per binning CTA
#define EPART 8        // per-segment partitions in the reduction kernel
#define NODE_CTAS 500
#define NPB  100       // nodes per node-CTA

// ---------------- scratch (device globals: no allocation allowed) ----------------
__device__ float g_xsum[BB * DN];        // node feature sums per graph
__device__ int   g_xcnt[BB];             // nodes per graph
__device__ float g_esum[BB * DE];        // edge feature sums per graph
__device__ int   g_ecnt[BB];             // edges per graph (also bucket allocator)
__device__ int   g_bucket[BB * CAP];     // edge ids bucketed by segment
__device__ float g_h[BB * HID];          // post-GEMM1 hidden
__device__ float g_bns[HID], g_bnsq[HID];// BN partial sums
__device__ int   g_idx64;                // 1 if indices are int64, 0 if int32

// dtype-agnostic index load
__device__ __forceinline__ int ld_idx(const void* p, long long i, int is64) {
    return is64 ? (int)((const long long*)p)[i] : ((const int*)p)[i];
}

// ---------------- K0: zero scratch + detect index width ----------------
__global__ void k_zero_detect(const int* __restrict__ ei32) {
    int gid = blockIdx.x * blockDim.x + threadIdx.x;
    int stride = gridDim.x * blockDim.x;
    for (int i = gid; i < BB * DN; i += stride) g_xsum[i] = 0.f;
    for (int i = gid; i < BB * DE; i += stride) g_esum[i] = 0.f;
    if (blockIdx.x == 0) {
        int t = threadIdx.x;
        for (int i = t; i < BB; i += 256) { g_xcnt[i] = 0; g_ecnt[i] = 0; }
        for (int i = t; i < HID; i += 256) { g_bns[i] = 0.f; g_bnsq[i] = 0.f; }
        // int64 detection: odd 32-bit words of first 1024 entries all zero <=> int64
        int nz = 0;
        for (int i = t; i < 1024; i += 256) nz |= ei32[2 * i + 1];
        __shared__ int snz;
        if (t == 0) snz = 0;
        __syncthreads();
        if (nz) atomicOr(&snz, 1);
        __syncthreads();
        if (t == 0) g_idx64 = snz ? 0 : 1;
    }
}

// ---------------- K1: FUSED node scatter-mean + edge bucketing ----------------
// CTAs [0, NODE_CTAS): node aggregation (batch sorted -> run compression with
//   smem-staged segment ids and a branchless, pipelineable inner loop).
// CTAs [NODE_CTAS, NODE_CTAS+EBLK): edge binning with 2-way split histogram.
// Fusion overlaps the two independent latency-bound phases in one wave.
__global__ void __launch_bounds__(256) k_node_bucket(const float* __restrict__ x,
                                                     const void* __restrict__ batch,
                                                     const void* __restrict__ eidx) {
    const int is64 = g_idx64;
    int t = threadIdx.x;

    if (blockIdx.x < NODE_CTAS) {
        // ---- node path: thread t owns feature dim t (DN=256=blockDim) ----
        __shared__ int sseg[NPB];
        int n0 = blockIdx.x * NPB;
        int len = min(NPB, NN - n0);
        if (t < len) sseg[t] = ld_idx(batch, n0 + t, is64);
        __syncthreads();
        int pos = 0;
        while (pos < len) {
            int s = sseg[pos];
            int end = pos + 1;
            while (end < len && sseg[end] == s) end++;   // thread-uniform scan
            float acc = 0.f;
            int m = n0 + pos, mend = n0 + end;
            for (; m + 3 < mend; m += 4) {               // branchless unroll-4: high MLP
                acc += x[(size_t)m * DN + t]
                     + x[(size_t)(m + 1) * DN + t]
                     + x[(size_t)(m + 2) * DN + t]
                     + x[(size_t)(m + 3) * DN + t];
            }
            for (; m < mend; m++) acc += x[(size_t)m * DN + t];
            atomicAdd(&g_xsum[s * DN + t], acc);
            if (t == 0) atomicAdd(&g_xcnt[s], end - pos);
            pos = end;
        }
    } else {
        // ---- bucket path ----
        __shared__ int shist[2][BB];         // split histogram: threads 0-127 / 128-255
        __shared__ int sbase2[2][BB];        // per-half scatter bases
        __shared__ unsigned short ssegs[EPB];
        int b = blockIdx.x - NODE_CTAS;
        int e0 = b * EPB;
        int half = t >> 7;                   // 0 for threads 0-127, 1 for 128-255
        for (int s = t; s < BB; s += 256) { shist[0][s] = 0; shist[1][s] = 0; }
        __syncthreads();
        // phase 1: segment per edge + split local histogram
        for (int it = t; it < EPB; it += 256) {
            int c = ld_idx(eidx, (long long)EE + (e0 + it), is64);  // col
            int s = ld_idx(batch, c, is64);
            ssegs[it] = (unsigned short)s;
            atomicAdd(&shist[half][s], 1);
        }
        __syncthreads();
        // phase 2: claim contiguous global ranges (1 global atomic per present seg)
        for (int s = t; s < BB; s += 256) {
            int c0 = shist[0][s], c1 = shist[1][s];
            int n = c0 + c1;
            int base = n ? atomicAdd(&g_ecnt[s], n) : 0;
            sbase2[0][s] = base;
            sbase2[1][s] = base + c0;
            shist[0][s] = 0; shist[1][s] = 0;
        }
        __syncthreads();
        // phase 3: scatter edge ids
        for (int it = t; it < EPB; it += 256) {
            int s = ssegs[it];
            int r = atomicAdd(&shist[half][s], 1);
            int pos = sbase2[half][s] + r;
            if (pos < CAP) g_bucket[s * CAP + pos] = e0 + it;
        }
    }
}

// ---------------- K3: per-segment edge reduction, 8-way partitioned ----------
// grid (BB, EPART). Atomic-free register accumulation per partition; edge ids
// for iteration n+1 prefetched during n (hides the ~234cyc L2 id-load latency).
__global__ void __launch_bounds__(256) k_eaggr(const float* __restrict__ ea) {
    __shared__ float4 sacc[8][32];
    int s = blockIdx.x;
    int p = blockIdx.y;
    int w = threadIdx.x >> 5, lane = threadIdx.x & 31;
    int cnt = min(g_ecnt[s], CAP);
    int i0 = (cnt * p) / EPART;
    int i1 = (cnt * (p + 1)) / EPART;
    const int* bkt = &g_bucket[s * CAP];
    float4 a = make_float4(0.f, 0.f, 0.f, 0.f);
    int i = i0 + w;
    int e0 = 0, e1 = 0, e2 = 0, e3 = 0;
    bool have = (i + 24 < i1);
    if (have) {
        e0 = bkt[i]; e1 = bkt[i + 8]; e2 = bkt[i + 16]; e3 = bkt[i + 24];
    }
    while (have) {
        int ni = i + 32;
        bool nhave = (ni + 24 < i1);
        int f0 = 0, f1 = 0, f2 = 0, f3 = 0;
        if (nhave) {
            f0 = bkt[ni]; f1 = bkt[ni + 8]; f2 = bkt[ni + 16]; f3 = bkt[ni + 24];
        }
        float4 v0 = ((const float4*)(ea + (long long)e0 * DE))[lane];
        float4 v1 = ((const float4*)(ea + (long long)e1 * DE))[lane];
        float4 v2 = ((const float4*)(ea + (long long)e2 * DE))[lane];
        float4 v3 = ((const float4*)(ea + (long long)e3 * DE))[lane];
        a.x += v0.x + v1.x + v2.x + v3.x;
        a.y += v0.y + v1.y + v2.y + v3.y;
        a.z += v0.z + v1.z + v2.z + v3.z;
        a.w += v0.w + v1.w + v2.w + v3.w;
        i = ni; e0 = f0; e1 = f1; e2 = f2; e3 = f3; have = nhave;
    }
    for (; i < i1; i += 8) {
        int e = bkt[i];
        float4 v = ((const float4*)(ea + (long long)e * DE))[lane];
        a.x += v.x; a.y += v.y; a.z += v.z; a.w += v.w;
    }
    sacc[w][lane] = a;
    __syncthreads();
    if (w == 0) {
        float4 tt = sacc[0][lane];
        #pragma unroll
        for (int j = 1; j < 8; j++) {
            float4 v = sacc[j][lane];
            tt.x += v.x; tt.y += v.y; tt.z += v.z; tt.w += v.w;
        }
        float* dst = &g_esum[s * DE + lane * 4];
        atomicAdd(dst + 0, tt.x);
        atomicAdd(dst + 1, tt.y);
        atomicAdd(dst + 2, tt.z);
        atomicAdd(dst + 3, tt.w);
    }
}

// ---------------- K5: GEMM1 with fused concat-build + BN partial stats -------
__global__ void __launch_bounds__(128) k_gemm1(const float* __restrict__ u,
                                               const float* __restrict__ W1,
                                               const float* __restrict__ b1) {
    __shared__ __align__(16) float sA[8 * DIN];
    __shared__ float sinvx[8], sinve[8];
    int r0 = blockIdx.y * 8;
    int col = blockIdx.x * 128 + threadIdx.x;
    if (threadIdx.x < 8) {
        int row = r0 + threadIdx.x;
        sinvx[threadIdx.x] = 1.f / (float)max(g_xcnt[row], 1);
        sinve[threadIdx.x] = 1.f / (float)max(g_ecnt[row], 1);
    }
    __syncthreads();
    for (int i = threadIdx.x; i < 8 * DIN; i += 128) {
        int r = i >> 9, k = i & (DIN - 1);
        int row = r0 + r;
        float v;
        if (k < 128)       v = u[row * DU + k];
        else if (k < 384)  v = g_xsum[row * DN + (k - 128)] * sinvx[r];
        else               v = g_esum[row * DE + (k - 384)] * sinve[r];
        sA[i] = v;
    }
    __syncthreads();
    float acc[8];
    #pragma unroll
    for (int r = 0; r < 8; r++) acc[r] = 0.f;
    for (int k = 0; k < DIN; k += 4) {
        float w0 = __ldg(&W1[(k + 0) * HID + col]);
        float w1 = __ldg(&W1[(k + 1) * HID + col]);
        float w2 = __ldg(&W1[(k + 2) * HID + col]);
        float w3 = __ldg(&W1[(k + 3) * HID + col]);
        #pragma unroll
        for (int r = 0; r < 8; r++) {
            float4 av = *(const float4*)&sA[r * DIN + k];
            acc[r] += av.x * w0 + av.y * w1 + av.z * w2 + av.w * w3;
        }
    }
    float bb = b1[col];
    float ps = 0.f, psq = 0.f;
    #pragma unroll
    for (int r = 0; r < 8; r++) {
        float v = acc[r] + bb;
        g_h[(r0 + r) * HID + col] = v;
        ps += v; psq += v * v;
    }
    atomicAdd(&g_bns[col], ps);
    atomicAdd(&g_bnsq[col], psq);
}

// ---------------- K8: GEMM2 with fused BN-finalize + BN+ReLU on input read ---
__global__ void __launch_bounds__(128) k_gemm2(const float* __restrict__ gamma,
                                               const float* __restrict__ beta,
                                               const float* __restrict__ W2,
                                               const float* __restrict__ b2,
                                               float* __restrict__ out) {
    __shared__ __align__(16) float sA[8 * HID];
    __shared__ float sscale[HID], sshift[HID];
    int r0 = blockIdx.y * 8;
    int col = threadIdx.x;  // 128 cols
    for (int j = threadIdx.x; j < HID; j += 128) {
        float m = g_bns[j] * (1.f / (float)BB);
        float var = g_bnsq[j] * (1.f / (float)BB) - m * m;
        float inv = rsqrtf(var + 1e-5f);
        float sc = gamma[j] * inv;
        sscale[j] = sc;
        sshift[j] = beta[j] - m * sc;
    }
    __syncthreads();
    for (int i = threadIdx.x; i < 8 * HID; i += 128) {
        int k = i & (HID - 1);
        float v = g_h[r0 * HID + i] * sscale[k] + sshift[k];
        sA[i] = fmaxf(v, 0.f);
    }
    __syncthreads();
    float acc[8];
    #pragma unroll
    for (int r = 0; r < 8; r++) acc[r] = 0.f;
    for (int k = 0; k < HID; k += 4) {
        float w0 = __ldg(&W2[(k + 0) * DOUT + col]);
        float w1 = __ldg(&W2[(k + 1) * DOUT + col]);
        float w2 = __ldg(&W2[(k + 2) * DOUT + col]);
        float w3 = __ldg(&W2[(k + 3) * DOUT + col]);
        #pragma unroll
        for (int r = 0; r < 8; r++) {
            float4 av = *(const float4*)&sA[r * HID + k];
            acc[r] += av.x * w0 + av.y * w1 + av.z * w2 + av.w * w3;
        }
    }
    float bb = b2[col];
    #pragma unroll
    for (int r = 0; r < 8; r++) out[(r0 + r) * DOUT + col] = acc[r] + bb;
}

// ---------------- launch ----------------
extern "C" void kernel_launch(void* const* d_in, const int* in_sizes, int n_in,
                              void* d_out, int out_size) {
    const float* x  = (const float*)d_in[0];
    const void*  ei = d_in[1];                  // edge_index [2, E] (int32 or int64)
    const float* ea = (const float*)d_in[2];
    const float* u  = (const float*)d_in[3];
    const void*  bt = (const void*)d_in[4];     // batch [N] sorted
    const float* W1 = (const float*)d_in[5];
    const float* b1 = (const float*)d_in[6];
    const float* ga = (const float*)d_in[7];
    const float* be = (const float*)d_in[8];
    const float* W2 = (const float*)d_in[9];
    const float* b2 = (const float*)d_in[10];

    k_zero_detect<<<256, 256>>>((const int*)ei);
    k_node_bucket<<<NODE_CTAS + EBLK, 256>>>(x, bt, ei);
    k_eaggr<<<dim3(BB, EPART), 256>>>(ea);
    k_gemm1<<<dim3(4, 64), 128>>>(u, W1, b1);
    k_gemm2<<<dim3(1, 64), 128>>>(ga, be, W2, b2, (float*)d_out);
}